// round 6
// baseline (speedup 1.0000x reference)
#include <cuda_runtime.h>
#include <math.h>

// Problem constants
#define BB   32
#define LSEQ 2048
#define DD   256
#define HH   64
#define YY   256
#define NP   64   // pooling partials per batch (16 l-chunks x 4 row-groups)

// Scratch (device globals — no allocation allowed)
__device__ float g_z[(size_t)BB * LSEQ * HH];      // 16 MB: z = x@w1a + b1 (shared by both passes)
__device__ float g_slog[BB * LSEQ];
__device__ float g_elog[BB * LSEQ];
__device__ float g_yte[BB * HH];
__device__ float g_pool_part[BB * NP * DD];

// tanh via MUFU.EX2 path: 1 - 2/(1+e^{2x}). Safe at both tails
// (x>>0: 1-2/inf=1; x<<0: 1-2/1=-1). Abs err ~1e-7.
__device__ __forceinline__ float fast_tanh(float x)
{
    return 1.f - __fdividef(2.f, 1.f + __expf(2.f * x));
}

// ---------------------------------------------------------------------------
// Main GEMM + s-score epilogue. Double-buffered smem pipeline, K_CHUNK=16.
// Per CTA: one batch b, 128 rows of L. z[128][64] = x_tile @ w1a (+b1) cached
// to g_z, plus s-logits. y_ts is recomputed per-CTA in the prologue (folds the
// old k_yts kernel). 256 threads; each owns rows rg+32i (i<4) and contiguous
// column octet c8*8..+7 (Wc reads = 2x LDS.128 per k).
// ---------------------------------------------------------------------------
__global__ __launch_bounds__(256) void k_gemm_score(
    const float* __restrict__ x, const unsigned char* __restrict__ xmask,
    const int* __restrict__ actions,
    const float* __restrict__ w1, const float* __restrict__ b1,
    const float* __restrict__ v,
    const float* __restrict__ c0,
    const float* __restrict__ w2, const float* __restrict__ b2)
{
    __shared__ float Xs[2][16][130];   // k-major x tile, pad 130 (conflict-free STS+LDS)
    __shared__ float Wc[2][16][64];    // 16-k chunk of w1a, double buffered
    __shared__ float red4[4][64];
    __shared__ float ysv[64];          // y_ts for this batch

    const int b  = blockIdx.y;
    const int l0 = blockIdx.x * 128;
    const int a  = actions[b];
    const float* wbase = w1 + (size_t)a * DD * HH;
    const float* xb    = x + ((size_t)b * LSEQ + l0) * DD;

    const int tid = threadIdx.x;
    const int c8 = tid & 7, rg = tid >> 3;        // compute mapping
    const int kk = tid & 3, l4 = tid >> 2;        // X load mapping (16-k chunk)
    const int hw = tid & 15, kwid = tid >> 4;     // W load mapping

    // ---- prologue: y_ts[h] = sum_d c0[b,d]*w2[a,d,h] + b2[a,h] (4-way d-split)
    {
        int h = tid & 63, q = tid >> 6;
        const float* w2p = w2 + (size_t)a * DD * HH + h;
        const float* yb  = c0 + b * DD;
        float ya = 0.f;
        #pragma unroll 8
        for (int d = q * 64; d < q * 64 + 64; d++) ya += yb[d] * w2p[(size_t)d * HH];
        red4[q][h] = ya;
    }

    float acc[4][8];
    #pragma unroll
    for (int i = 0; i < 4; i++)
        #pragma unroll
        for (int j = 0; j < 8; j++) acc[i][j] = 0.f;

    // Prefetch chunk 0 into registers
    float4 xv[2], wv;
    #pragma unroll
    for (int p = 0; p < 2; p++)
        xv[p] = *(const float4*)(xb + (size_t)(l4 + 64 * p) * DD + kk * 4);
    wv = *(const float4*)(wbase + (size_t)kwid * HH + hw * 4);

    __syncthreads();   // red4 ready
    {
        int h = tid & 63, q = tid >> 6;
        if (q == 0)
            ysv[h] = red4[0][h] + red4[1][h] + red4[2][h] + red4[3][h] + b2[a * HH + h];
    }

    // Stage chunk 0 into buffer 0
    #pragma unroll
    for (int p = 0; p < 2; p++) {
        int row = l4 + 64 * p;
        Xs[0][kk * 4 + 0][row] = xv[p].x;
        Xs[0][kk * 4 + 1][row] = xv[p].y;
        Xs[0][kk * 4 + 2][row] = xv[p].z;
        Xs[0][kk * 4 + 3][row] = xv[p].w;
    }
    *(float4*)&Wc[0][kwid][hw * 4] = wv;
    __syncthreads();

    for (int kc = 0; kc < 16; kc++) {
        const int buf = kc & 1;
        // Prefetch next chunk (latency overlaps the FFMA block below)
        if (kc < 15) {
            int koff = (kc + 1) * 16;
            #pragma unroll
            for (int p = 0; p < 2; p++)
                xv[p] = *(const float4*)(xb + (size_t)(l4 + 64 * p) * DD + koff + kk * 4);
            wv = *(const float4*)(wbase + (size_t)(koff + kwid) * HH + hw * 4);
        }

        #pragma unroll
        for (int k = 0; k < 16; k++) {
            float aa[4];
            #pragma unroll
            for (int i = 0; i < 4; i++) aa[i] = Xs[buf][k][rg + 32 * i];
            float4 w0 = *(const float4*)&Wc[buf][k][c8 * 8];
            float4 w1v = *(const float4*)&Wc[buf][k][c8 * 8 + 4];
            #pragma unroll
            for (int i = 0; i < 4; i++) {
                acc[i][0] += aa[i] * w0.x;  acc[i][1] += aa[i] * w0.y;
                acc[i][2] += aa[i] * w0.z;  acc[i][3] += aa[i] * w0.w;
                acc[i][4] += aa[i] * w1v.x; acc[i][5] += aa[i] * w1v.y;
                acc[i][6] += aa[i] * w1v.z; acc[i][7] += aa[i] * w1v.w;
            }
        }

        if (kc < 15) {
            const int nb = buf ^ 1;
            #pragma unroll
            for (int p = 0; p < 2; p++) {
                int row = l4 + 64 * p;
                Xs[nb][kk * 4 + 0][row] = xv[p].x;
                Xs[nb][kk * 4 + 1][row] = xv[p].y;
                Xs[nb][kk * 4 + 2][row] = xv[p].z;
                Xs[nb][kk * 4 + 3][row] = xv[p].w;
            }
            *(float4*)&Wc[nb][kwid][hw * 4] = wv;
            __syncthreads();
        }
    }

    // Epilogue: add b1, store z (STG.128), compute s-scores
    const int hb = c8 * 8;
    float4 bb0 = *(const float4*)(b1 + a * HH + hb);
    float4 bb1 = *(const float4*)(b1 + a * HH + hb + 4);
    float4 yt0 = *(const float4*)(&ysv[hb]);
    float4 yt1 = *(const float4*)(&ysv[hb + 4]);
    float4 vv0 = *(const float4*)(v + a * HH + hb);
    float4 vv1 = *(const float4*)(v + a * HH + hb + 4);

    float sp[4];
    #pragma unroll
    for (int i = 0; i < 4; i++) {
        int row = rg + 32 * i;
        float4 z0, z1;
        z0.x = acc[i][0] + bb0.x; z0.y = acc[i][1] + bb0.y;
        z0.z = acc[i][2] + bb0.z; z0.w = acc[i][3] + bb0.w;
        z1.x = acc[i][4] + bb1.x; z1.y = acc[i][5] + bb1.y;
        z1.z = acc[i][6] + bb1.z; z1.w = acc[i][7] + bb1.w;
        float* zr = g_z + ((size_t)b * LSEQ + l0 + row) * HH + hb;
        *(float4*)zr = z0;
        *(float4*)(zr + 4) = z1;
        float s;
        s  = vv0.x * fast_tanh(z0.x + yt0.x);
        s += vv0.y * fast_tanh(z0.y + yt0.y);
        s += vv0.z * fast_tanh(z0.z + yt0.z);
        s += vv0.w * fast_tanh(z0.w + yt0.w);
        s += vv1.x * fast_tanh(z1.x + yt1.x);
        s += vv1.y * fast_tanh(z1.y + yt1.y);
        s += vv1.z * fast_tanh(z1.z + yt1.z);
        s += vv1.w * fast_tanh(z1.w + yt1.w);
        sp[i] = s;
    }
    #pragma unroll
    for (int i = 0; i < 4; i++) {
        float s = sp[i];
        s += __shfl_xor_sync(0xffffffffu, s, 1);
        s += __shfl_xor_sync(0xffffffffu, s, 2);
        s += __shfl_xor_sync(0xffffffffu, s, 4);
        if (c8 == 0) {
            int l = l0 + rg + 32 * i;
            g_slog[b * LSEQ + l] = xmask[b * LSEQ + l] ? -1e30f : s;
        }
    }
}

// ---------------------------------------------------------------------------
// Row softmax over L=2048. which=0 -> g_slog, which=1 -> g_elog
// ---------------------------------------------------------------------------
__global__ __launch_bounds__(256) void k_softmax(int which, float* __restrict__ probs)
{
    __shared__ float red[256];
    int b = blockIdx.x, tid = threadIdx.x;
    const float* in = (which == 0 ? g_slog : g_elog) + b * LSEQ;
    float vals[8];
    float m = -INFINITY;
    #pragma unroll
    for (int i = 0; i < 8; i++) { vals[i] = in[tid + 256 * i]; m = fmaxf(m, vals[i]); }
    red[tid] = m; __syncthreads();
    for (int s = 128; s > 0; s >>= 1) { if (tid < s) red[tid] = fmaxf(red[tid], red[tid + s]); __syncthreads(); }
    m = red[0]; __syncthreads();
    float sum = 0.f;
    #pragma unroll
    for (int i = 0; i < 8; i++) { vals[i] = __expf(vals[i] - m); sum += vals[i]; }
    red[tid] = sum; __syncthreads();
    for (int s = 128; s > 0; s >>= 1) { if (tid < s) red[tid] += red[tid + s]; __syncthreads(); }
    float inv = 1.f / red[0];
    float* outp = probs + b * LSEQ;
    #pragma unroll
    for (int i = 0; i < 8; i++) outp[tid + 256 * i] = vals[i] * inv;
}

// ---------------------------------------------------------------------------
// attn_pool partials, two interleaved row-streams for 2x MLP.
// grid (16, B), 256 threads: d4 = tid&63 owns a float4 of D; lg = tid>>6 owns
// 32 of the CTA's 128 l-rows (processed as rows l and l+16 in parallel).
// ---------------------------------------------------------------------------
__global__ __launch_bounds__(256) void k_pool(const float* __restrict__ x,
                                              const float* __restrict__ probs)
{
    __shared__ float ps[128];
    int c = blockIdx.x, b = blockIdx.y, tid = threadIdx.x;
    int d4 = tid & 63, lg = tid >> 6;
    if (tid < 128) ps[tid] = probs[b * LSEQ + c * 128 + tid];
    __syncthreads();
    const float* xp = x + ((size_t)b * LSEQ + c * 128 + lg * 32) * DD + d4 * 4;
    const float* pp = ps + lg * 32;
    float4 accA = make_float4(0.f, 0.f, 0.f, 0.f);
    float4 accB = make_float4(0.f, 0.f, 0.f, 0.f);
    #pragma unroll 8
    for (int l = 0; l < 16; l++) {
        float4 xa = *(const float4*)(xp + (size_t)l * DD);
        float4 xc = *(const float4*)(xp + (size_t)(l + 16) * DD);
        float pa = pp[l], pc = pp[l + 16];
        accA.x += xa.x * pa; accA.y += xa.y * pa;
        accA.z += xa.z * pa; accA.w += xa.w * pa;
        accB.x += xc.x * pc; accB.y += xc.y * pc;
        accB.z += xc.z * pc; accB.w += xc.w * pc;
    }
    accA.x += accB.x; accA.y += accB.y; accA.z += accB.z; accA.w += accB.w;
    *(float4*)(&g_pool_part[((size_t)(b * 16 + c) * 4 + lg) * DD + d4 * 4]) = accA;
}

// ---------------------------------------------------------------------------
// SRU cell + y_t for the e-pass.
// ---------------------------------------------------------------------------
__global__ __launch_bounds__(256) void k_sru(const float* __restrict__ c0,
    const float* __restrict__ w_sru, const float* __restrict__ b_sru,
    const int* __restrict__ actions,
    const float* __restrict__ w2, const float* __restrict__ b2)
{
    __shared__ float pool[DD];
    __shared__ float state[YY];
    int b = blockIdx.x, tid = threadIdx.x;
    float acc0 = 0.f, acc1 = 0.f, acc2 = 0.f, acc3 = 0.f;
    #pragma unroll 4
    for (int c = 0; c < NP; c += 4) {
        acc0 += g_pool_part[((size_t)b * NP + c) * DD + tid];
        acc1 += g_pool_part[((size_t)b * NP + c + 1) * DD + tid];
        acc2 += g_pool_part[((size_t)b * NP + c + 2) * DD + tid];
        acc3 += g_pool_part[((size_t)b * NP + c + 3) * DD + tid];
    }
    pool[tid] = (acc0 + acc1) + (acc2 + acc3);
    __syncthreads();

    // u[:, tid] (x_tilde) and u[:, 256+tid] (f-gate pre-activation)
    float u0 = 0.f, u1 = 0.f;
    #pragma unroll 8
    for (int d = 0; d < DD; d++) {
        float pv = pool[d];
        u0 += pv * w_sru[d * 768 + tid];
        u1 += pv * w_sru[d * 768 + 256 + tid];
    }
    float f = 1.f / (1.f + __expf(-(u1 + b_sru[tid])));
    state[tid] = f * c0[b * DD + tid] + (1.f - f) * u0;
    __syncthreads();

    // y_te[b,h]: 4-way d-split
    int h = tid & 63, q = tid >> 6;
    int a = actions[b];
    const float* w = w2 + (size_t)a * DD * HH + h;
    float yt = 0.f;
    #pragma unroll 8
    for (int d = q * 64; d < q * 64 + 64; d++) yt += state[d] * w[(size_t)d * HH];
    __syncthreads();
    pool[tid] = yt;   // reuse smem as [4][64]
    __syncthreads();
    if (q == 0)
        g_yte[b * HH + h] = pool[h] + pool[64 + h] + pool[128 + h] + pool[192 + h]
                            + b2[a * HH + h];
}

// ---------------------------------------------------------------------------
// e-scores from cached z. float2 per lane, 4 rows per warp (32 rows per CTA).
// ---------------------------------------------------------------------------
__global__ __launch_bounds__(256) void k_escore(const unsigned char* __restrict__ xmask,
    const int* __restrict__ actions, const float* __restrict__ v)
{
    int b = blockIdx.y;
    int wid = threadIdx.x >> 5, lane = threadIdx.x & 31;
    int a = actions[b];
    float2 yv = *(const float2*)(&g_yte[b * HH + 2 * lane]);
    float2 vv = *(const float2*)(v + a * HH + 2 * lane);
    #pragma unroll
    for (int r = 0; r < 4; r++) {
        int l = blockIdx.x * 32 + wid * 4 + r;
        float2 z2 = *(const float2*)(&g_z[((size_t)b * LSEQ + l) * HH + 2 * lane]);
        float s = vv.x * fast_tanh(z2.x + yv.x) + vv.y * fast_tanh(z2.y + yv.y);
        #pragma unroll
        for (int o = 16; o > 0; o >>= 1) s += __shfl_xor_sync(0xffffffffu, s, o);
        if (lane == 0) g_elog[b * LSEQ + l] = xmask[b * LSEQ + l] ? -1e30f : s;
    }
}

// ---------------------------------------------------------------------------
extern "C" void kernel_launch(void* const* d_in, const int* in_sizes, int n_in,
                              void* d_out, int out_size)
{
    const float*         x      = (const float*)d_in[0];
    const unsigned char* xmask  = (const unsigned char*)d_in[1];
    const float*         c0     = (const float*)d_in[2];
    const int*           actions= (const int*)d_in[3];
    const float*         w1     = (const float*)d_in[4];
    const float*         b1     = (const float*)d_in[5];
    const float*         w2     = (const float*)d_in[6];
    const float*         b2     = (const float*)d_in[7];
    const float*         v      = (const float*)d_in[8];
    const float*         w_sru  = (const float*)d_in[9];
    const float*         b_sru  = (const float*)d_in[10];
    float* out = (float*)d_out;   // [0:65536) = s_probs, [65536:131072) = e_probs

    k_gemm_score<<<dim3(LSEQ / 128, BB), 256>>>(x, xmask, actions, w1, b1, v, c0, w2, b2);
    k_softmax<<<BB, 256>>>(0, out);                        // s_probs
    k_pool<<<dim3(16, BB), 256>>>(x, out);
    k_sru<<<BB, 256>>>(c0, w_sru, b_sru, actions, w2, b2);
    k_escore<<<dim3(LSEQ / 32, BB), 256>>>(xmask, actions, v);
    k_softmax<<<BB, 256>>>(1, out + BB * LSEQ);            // e_probs
}

// round 7
// speedup vs baseline: 1.1190x; 1.1190x over previous
#include <cuda_runtime.h>
#include <math.h>

// Problem constants
#define BB   32
#define LSEQ 2048
#define DD   256
#define HH   64
#define YY   256
#define NP   64   // pooling partials per batch (16 l-chunks x 4 row-groups)

// Scratch (device globals — no allocation allowed)
__device__ float g_z[(size_t)BB * LSEQ * HH];      // 16 MB: z = x@w1a + b1 (shared by both passes)
__device__ float g_slog[BB * LSEQ];
__device__ float g_elog[BB * LSEQ];
__device__ float g_yte[BB * HH];
__device__ float g_pool_part[BB * NP * DD];

// tanh via MUFU.EX2 path: 1 - 2/(1+e^{2x}). Safe at both tails
// (x>>0: 1-2/inf=1; x<<0: 1-2/1=-1). Abs err ~1e-7.
__device__ __forceinline__ float fast_tanh(float x)
{
    return 1.f - __fdividef(2.f, 1.f + __expf(2.f * x));
}

// ---------------------------------------------------------------------------
// Main GEMM + s-score epilogue. Double-buffered smem pipeline, K_CHUNK=16.
// Per CTA: one batch b, 128 rows of L. z[128][64] = x_tile @ w1a (+b1) cached
// to g_z, plus s-logits. y_ts is recomputed per-CTA in the prologue.
// ---------------------------------------------------------------------------
__global__ __launch_bounds__(256) void k_gemm_score(
    const float* __restrict__ x, const unsigned char* __restrict__ xmask,
    const int* __restrict__ actions,
    const float* __restrict__ w1, const float* __restrict__ b1,
    const float* __restrict__ v,
    const float* __restrict__ c0,
    const float* __restrict__ w2, const float* __restrict__ b2)
{
    __shared__ float Xs[2][16][130];   // k-major x tile, pad 130 (conflict-free STS+LDS)
    __shared__ float Wc[2][16][64];    // 16-k chunk of w1a, double buffered
    __shared__ float red4[4][64];
    __shared__ float ysv[64];          // y_ts for this batch

    const int b  = blockIdx.y;
    const int l0 = blockIdx.x * 128;
    const int a  = actions[b];
    const float* wbase = w1 + (size_t)a * DD * HH;
    const float* xb    = x + ((size_t)b * LSEQ + l0) * DD;

    const int tid = threadIdx.x;
    const int c8 = tid & 7, rg = tid >> 3;        // compute mapping
    const int kk = tid & 3, l4 = tid >> 2;        // X load mapping (16-k chunk)
    const int hw = tid & 15, kwid = tid >> 4;     // W load mapping

    // ---- prologue: y_ts[h] = sum_d c0[b,d]*w2[a,d,h] + b2[a,h] (4-way d-split)
    {
        int h = tid & 63, q = tid >> 6;
        const float* w2p = w2 + (size_t)a * DD * HH + h;
        const float* yb  = c0 + b * DD;
        float ya = 0.f;
        #pragma unroll 8
        for (int d = q * 64; d < q * 64 + 64; d++) ya += yb[d] * w2p[(size_t)d * HH];
        red4[q][h] = ya;
    }

    float acc[4][8];
    #pragma unroll
    for (int i = 0; i < 4; i++)
        #pragma unroll
        for (int j = 0; j < 8; j++) acc[i][j] = 0.f;

    // Prefetch chunk 0 into registers
    float4 xv[2], wv;
    #pragma unroll
    for (int p = 0; p < 2; p++)
        xv[p] = *(const float4*)(xb + (size_t)(l4 + 64 * p) * DD + kk * 4);
    wv = *(const float4*)(wbase + (size_t)kwid * HH + hw * 4);

    __syncthreads();   // red4 ready
    {
        int h = tid & 63, q = tid >> 6;
        if (q == 0)
            ysv[h] = red4[0][h] + red4[1][h] + red4[2][h] + red4[3][h] + b2[a * HH + h];
    }

    // Stage chunk 0 into buffer 0
    #pragma unroll
    for (int p = 0; p < 2; p++) {
        int row = l4 + 64 * p;
        Xs[0][kk * 4 + 0][row] = xv[p].x;
        Xs[0][kk * 4 + 1][row] = xv[p].y;
        Xs[0][kk * 4 + 2][row] = xv[p].z;
        Xs[0][kk * 4 + 3][row] = xv[p].w;
    }
    *(float4*)&Wc[0][kwid][hw * 4] = wv;
    __syncthreads();

    for (int kc = 0; kc < 16; kc++) {
        const int buf = kc & 1;
        // Prefetch next chunk (latency overlaps the FFMA block below)
        if (kc < 15) {
            int koff = (kc + 1) * 16;
            #pragma unroll
            for (int p = 0; p < 2; p++)
                xv[p] = *(const float4*)(xb + (size_t)(l4 + 64 * p) * DD + koff + kk * 4);
            wv = *(const float4*)(wbase + (size_t)(koff + kwid) * HH + hw * 4);
        }

        #pragma unroll
        for (int k = 0; k < 16; k++) {
            float aa[4];
            #pragma unroll
            for (int i = 0; i < 4; i++) aa[i] = Xs[buf][k][rg + 32 * i];
            float4 w0 = *(const float4*)&Wc[buf][k][c8 * 8];
            float4 w1v = *(const float4*)&Wc[buf][k][c8 * 8 + 4];
            #pragma unroll
            for (int i = 0; i < 4; i++) {
                acc[i][0] += aa[i] * w0.x;  acc[i][1] += aa[i] * w0.y;
                acc[i][2] += aa[i] * w0.z;  acc[i][3] += aa[i] * w0.w;
                acc[i][4] += aa[i] * w1v.x; acc[i][5] += aa[i] * w1v.y;
                acc[i][6] += aa[i] * w1v.z; acc[i][7] += aa[i] * w1v.w;
            }
        }

        if (kc < 15) {
            const int nb = buf ^ 1;
            #pragma unroll
            for (int p = 0; p < 2; p++) {
                int row = l4 + 64 * p;
                Xs[nb][kk * 4 + 0][row] = xv[p].x;
                Xs[nb][kk * 4 + 1][row] = xv[p].y;
                Xs[nb][kk * 4 + 2][row] = xv[p].z;
                Xs[nb][kk * 4 + 3][row] = xv[p].w;
            }
            *(float4*)&Wc[nb][kwid][hw * 4] = wv;
            __syncthreads();
        }
    }

    // Epilogue: add b1, store z (STG.128), compute s-scores
    const int hb = c8 * 8;
    float4 bb0 = *(const float4*)(b1 + a * HH + hb);
    float4 bb1 = *(const float4*)(b1 + a * HH + hb + 4);
    float4 yt0 = *(const float4*)(&ysv[hb]);
    float4 yt1 = *(const float4*)(&ysv[hb + 4]);
    float4 vv0 = *(const float4*)(v + a * HH + hb);
    float4 vv1 = *(const float4*)(v + a * HH + hb + 4);

    float sp[4];
    #pragma unroll
    for (int i = 0; i < 4; i++) {
        int row = rg + 32 * i;
        float4 z0, z1;
        z0.x = acc[i][0] + bb0.x; z0.y = acc[i][1] + bb0.y;
        z0.z = acc[i][2] + bb0.z; z0.w = acc[i][3] + bb0.w;
        z1.x = acc[i][4] + bb1.x; z1.y = acc[i][5] + bb1.y;
        z1.z = acc[i][6] + bb1.z; z1.w = acc[i][7] + bb1.w;
        float* zr = g_z + ((size_t)b * LSEQ + l0 + row) * HH + hb;
        *(float4*)zr = z0;
        *(float4*)(zr + 4) = z1;
        float s;
        s  = vv0.x * fast_tanh(z0.x + yt0.x);
        s += vv0.y * fast_tanh(z0.y + yt0.y);
        s += vv0.z * fast_tanh(z0.z + yt0.z);
        s += vv0.w * fast_tanh(z0.w + yt0.w);
        s += vv1.x * fast_tanh(z1.x + yt1.x);
        s += vv1.y * fast_tanh(z1.y + yt1.y);
        s += vv1.z * fast_tanh(z1.z + yt1.z);
        s += vv1.w * fast_tanh(z1.w + yt1.w);
        sp[i] = s;
    }
    #pragma unroll
    for (int i = 0; i < 4; i++) {
        float s = sp[i];
        s += __shfl_xor_sync(0xffffffffu, s, 1);
        s += __shfl_xor_sync(0xffffffffu, s, 2);
        s += __shfl_xor_sync(0xffffffffu, s, 4);
        if (c8 == 0) {
            int l = l0 + rg + 32 * i;
            g_slog[b * LSEQ + l] = xmask[b * LSEQ + l] ? -1e30f : s;
        }
    }
}

// ---------------------------------------------------------------------------
// Row softmax over L=2048. which=0 -> g_slog, which=1 -> g_elog
// ---------------------------------------------------------------------------
__global__ __launch_bounds__(256) void k_softmax(int which, float* __restrict__ probs)
{
    __shared__ float red[256];
    int b = blockIdx.x, tid = threadIdx.x;
    const float* in = (which == 0 ? g_slog : g_elog) + b * LSEQ;
    float vals[8];
    float m = -INFINITY;
    #pragma unroll
    for (int i = 0; i < 8; i++) { vals[i] = in[tid + 256 * i]; m = fmaxf(m, vals[i]); }
    red[tid] = m; __syncthreads();
    for (int s = 128; s > 0; s >>= 1) { if (tid < s) red[tid] = fmaxf(red[tid], red[tid + s]); __syncthreads(); }
    m = red[0]; __syncthreads();
    float sum = 0.f;
    #pragma unroll
    for (int i = 0; i < 8; i++) { vals[i] = __expf(vals[i] - m); sum += vals[i]; }
    red[tid] = sum; __syncthreads();
    for (int s = 128; s > 0; s >>= 1) { if (tid < s) red[tid] += red[tid + s]; __syncthreads(); }
    float inv = 1.f / red[0];
    float* outp = probs + b * LSEQ;
    #pragma unroll
    for (int i = 0; i < 8; i++) outp[tid + 256 * i] = vals[i] * inv;
}

// ---------------------------------------------------------------------------
// attn_pool partials, four interleaved row-streams (16 LDG.128 in flight).
// grid (16, B), 256 threads: d4 = tid&63 owns a float4 of D; lg = tid>>6 owns
// 32 of the CTA's 128 l-rows (rows l, l+8, l+16, l+24 in parallel).
// ---------------------------------------------------------------------------
__global__ __launch_bounds__(256) void k_pool(const float* __restrict__ x,
                                              const float* __restrict__ probs)
{
    __shared__ float ps[128];
    int c = blockIdx.x, b = blockIdx.y, tid = threadIdx.x;
    int d4 = tid & 63, lg = tid >> 6;
    if (tid < 128) ps[tid] = probs[b * LSEQ + c * 128 + tid];
    __syncthreads();
    const float* xp = x + ((size_t)b * LSEQ + c * 128 + lg * 32) * DD + d4 * 4;
    const float* pp = ps + lg * 32;
    float4 aA = make_float4(0.f, 0.f, 0.f, 0.f);
    float4 aB = make_float4(0.f, 0.f, 0.f, 0.f);
    float4 aC = make_float4(0.f, 0.f, 0.f, 0.f);
    float4 aD = make_float4(0.f, 0.f, 0.f, 0.f);
    #pragma unroll
    for (int l = 0; l < 8; l += 2) {
        #pragma unroll
        for (int u = 0; u < 2; u++) {
            int li = l + u;
            float4 xa = *(const float4*)(xp + (size_t)li * DD);
            float4 xb2 = *(const float4*)(xp + (size_t)(li + 8) * DD);
            float4 xc = *(const float4*)(xp + (size_t)(li + 16) * DD);
            float4 xd = *(const float4*)(xp + (size_t)(li + 24) * DD);
            float pa = pp[li], pb = pp[li + 8], pc = pp[li + 16], pd = pp[li + 24];
            aA.x += xa.x * pa; aA.y += xa.y * pa; aA.z += xa.z * pa; aA.w += xa.w * pa;
            aB.x += xb2.x * pb; aB.y += xb2.y * pb; aB.z += xb2.z * pb; aB.w += xb2.w * pb;
            aC.x += xc.x * pc; aC.y += xc.y * pc; aC.z += xc.z * pc; aC.w += xc.w * pc;
            aD.x += xd.x * pd; aD.y += xd.y * pd; aD.z += xd.z * pd; aD.w += xd.w * pd;
        }
    }
    aA.x = (aA.x + aB.x) + (aC.x + aD.x);
    aA.y = (aA.y + aB.y) + (aC.y + aD.y);
    aA.z = (aA.z + aB.z) + (aC.z + aD.z);
    aA.w = (aA.w + aB.w) + (aC.w + aD.w);
    *(float4*)(&g_pool_part[((size_t)(b * 16 + c) * 4 + lg) * DD + d4 * 4]) = aA;
}

// ---------------------------------------------------------------------------
// SRU cell + y_te, rebuilt for latency. 512 threads, one CTA per batch.
// Phase A: partial-sum gather with 32 loads in flight (2-way c-split).
// Phase B: one u-output per thread (tid indexes w_sru col directly), unroll 32.
// Phase C: y_te with 8-way d-split (32-long chains) + smem tree.
// ---------------------------------------------------------------------------
__global__ __launch_bounds__(512) void k_sru(const float* __restrict__ c0,
    const float* __restrict__ w_sru, const float* __restrict__ b_sru,
    const int* __restrict__ actions,
    const float* __restrict__ w2, const float* __restrict__ b2)
{
    __shared__ float pool[DD];
    __shared__ float uu[2 * YY];     // scratch in phase A; u0|u1 in phase B
    __shared__ float state[YY];
    __shared__ float red8[8][HH];
    const int b = blockIdx.x, tid = threadIdx.x;

    // ---- Phase A: pool[d] = sum_{p<64} pool_part[b][p][d]; 2-way p-split.
    {
        int d = tid & 255, hf = tid >> 8;   // hf in {0,1}: partials [0,32) / [32,64)
        const float* pp = g_pool_part + (size_t)b * NP * DD + (size_t)hf * 32 * DD + d;
        float a0 = 0.f, a1 = 0.f, a2 = 0.f, a3 = 0.f;
        #pragma unroll
        for (int c = 0; c < 32; c += 4) {
            a0 += pp[(size_t)c * DD];
            a1 += pp[(size_t)(c + 1) * DD];
            a2 += pp[(size_t)(c + 2) * DD];
            a3 += pp[(size_t)(c + 3) * DD];
        }
        uu[tid] = (a0 + a1) + (a2 + a3);
    }
    __syncthreads();
    if (tid < DD) pool[tid] = uu[tid] + uu[tid + 256];
    __syncthreads();

    // ---- Phase B: u[tid] = sum_d pool[d] * w_sru[d][tid], tid < 512.
    // (w_sru cols [0,256)=x_tilde, [256,512)=f-gate; col 512+ unused.)
    {
        const float* wp = w_sru + tid;
        float u0 = 0.f, u1 = 0.f;
        #pragma unroll 16
        for (int d = 0; d < DD; d += 2) {
            u0 += pool[d]     * wp[(size_t)d * 768];
            u1 += pool[d + 1] * wp[(size_t)(d + 1) * 768];
        }
        uu[tid] = u0 + u1;
    }
    __syncthreads();
    if (tid < YY) {
        float f = 1.f / (1.f + __expf(-(uu[YY + tid] + b_sru[tid])));
        state[tid] = f * c0[b * DD + tid] + (1.f - f) * uu[tid];
    }
    __syncthreads();

    // ---- Phase C: y_te[h] = sum_d state[d] * w2[a][d][h], 8-way d-split.
    const int a = actions[b];
    {
        int h = tid & 63, q = tid >> 6;   // q in 0..7
        const float* w = w2 + (size_t)a * DD * HH + h;
        float yt = 0.f;
        #pragma unroll
        for (int d = q * 32; d < q * 32 + 32; d++) yt += state[d] * w[(size_t)d * HH];
        red8[q][h] = yt;
    }
    __syncthreads();
    if (tid < HH) {
        float s = 0.f;
        #pragma unroll
        for (int q = 0; q < 8; q++) s += red8[q][tid];
        g_yte[b * HH + tid] = s + b2[a * HH + tid];
    }
}

// ---------------------------------------------------------------------------
// e-scores from cached z. float2 per lane, 4 rows per warp (32 rows per CTA).
// ---------------------------------------------------------------------------
__global__ __launch_bounds__(256) void k_escore(const unsigned char* __restrict__ xmask,
    const int* __restrict__ actions, const float* __restrict__ v)
{
    int b = blockIdx.y;
    int wid = threadIdx.x >> 5, lane = threadIdx.x & 31;
    int a = actions[b];
    float2 yv = *(const float2*)(&g_yte[b * HH + 2 * lane]);
    float2 vv = *(const float2*)(v + a * HH + 2 * lane);
    #pragma unroll
    for (int r = 0; r < 4; r++) {
        int l = blockIdx.x * 32 + wid * 4 + r;
        float2 z2 = *(const float2*)(&g_z[((size_t)b * LSEQ + l) * HH + 2 * lane]);
        float s = vv.x * fast_tanh(z2.x + yv.x) + vv.y * fast_tanh(z2.y + yv.y);
        #pragma unroll
        for (int o = 16; o > 0; o >>= 1) s += __shfl_xor_sync(0xffffffffu, s, o);
        if (lane == 0) g_elog[b * LSEQ + l] = xmask[b * LSEQ + l] ? -1e30f : s;
    }
}

// ---------------------------------------------------------------------------
extern "C" void kernel_launch(void* const* d_in, const int* in_sizes, int n_in,
                              void* d_out, int out_size)
{
    const float*         x      = (const float*)d_in[0];
    const unsigned char* xmask  = (const unsigned char*)d_in[1];
    const float*         c0     = (const float*)d_in[2];
    const int*           actions= (const int*)d_in[3];
    const float*         w1     = (const float*)d_in[4];
    const float*         b1     = (const float*)d_in[5];
    const float*         w2     = (const float*)d_in[6];
    const float*         b2     = (const float*)d_in[7];
    const float*         v      = (const float*)d_in[8];
    const float*         w_sru  = (const float*)d_in[9];
    const float*         b_sru  = (const float*)d_in[10];
    float* out = (float*)d_out;   // [0:65536) = s_probs, [65536:131072) = e_probs

    k_gemm_score<<<dim3(LSEQ / 128, BB), 256>>>(x, xmask, actions, w1, b1, v, c0, w2, b2);
    k_softmax<<<BB, 256>>>(0, out);                        // s_probs
    k_pool<<<dim3(16, BB), 256>>>(x, out);
    k_sru<<<BB, 512>>>(c0, w_sru, b_sru, actions, w2, b2);
    k_escore<<<dim3(LSEQ / 32, BB), 256>>>(xmask, actions, v);
    k_softmax<<<BB, 256>>>(1, out + BB * LSEQ);            // e_probs
}

// round 8
// speedup vs baseline: 1.1495x; 1.0272x over previous
#include <cuda_runtime.h>
#include <math.h>

// Problem constants
#define BB   32
#define LSEQ 2048
#define DD   256
#define HH   64
#define YY   256
#define NP   64   // pooling partials per batch (16 l-chunks x 4 row-groups)

// Scratch (device globals — no allocation allowed)
__device__ float g_z[(size_t)BB * LSEQ * HH];      // 16 MB: z = x@w1a + b1 (shared by both passes)
__device__ float g_slog[BB * LSEQ];
__device__ float g_elog[BB * LSEQ];
__device__ float g_yte[BB * HH];
__device__ float g_pool_part[BB * NP * DD];

// tanh via MUFU.EX2 path: 1 - 2/(1+e^{2x}). Safe at both tails
// (x>>0: 1-2/inf=1; x<<0: 1-2/1=-1). Abs err ~1e-7.
__device__ __forceinline__ float fast_tanh(float x)
{
    return 1.f - __fdividef(2.f, 1.f + __expf(2.f * x));
}

// ---------------------------------------------------------------------------
// Main GEMM + s-score epilogue. Double-buffered smem pipeline, K_CHUNK=16.
// Per CTA: one batch b, 128 rows of L. z[128][64] = x_tile @ w1a (+b1) cached
// to g_z, plus s-logits. y_ts is recomputed per-CTA in the prologue.
// ---------------------------------------------------------------------------
__global__ __launch_bounds__(256) void k_gemm_score(
    const float* __restrict__ x, const unsigned char* __restrict__ xmask,
    const int* __restrict__ actions,
    const float* __restrict__ w1, const float* __restrict__ b1,
    const float* __restrict__ v,
    const float* __restrict__ c0,
    const float* __restrict__ w2, const float* __restrict__ b2)
{
    __shared__ float Xs[2][16][130];   // k-major x tile, pad 130 (conflict-free STS+LDS)
    __shared__ float Wc[2][16][64];    // 16-k chunk of w1a, double buffered
    __shared__ float red4[4][64];
    __shared__ float ysv[64];          // y_ts for this batch

    const int b  = blockIdx.y;
    const int l0 = blockIdx.x * 128;
    const int a  = actions[b];
    const float* wbase = w1 + (size_t)a * DD * HH;
    const float* xb    = x + ((size_t)b * LSEQ + l0) * DD;

    const int tid = threadIdx.x;
    const int c8 = tid & 7, rg = tid >> 3;        // compute mapping
    const int kk = tid & 3, l4 = tid >> 2;        // X load mapping (16-k chunk)
    const int hw = tid & 15, kwid = tid >> 4;     // W load mapping

    // ---- prologue: y_ts[h] = sum_d c0[b,d]*w2[a,d,h] + b2[a,h] (4-way d-split)
    {
        int h = tid & 63, q = tid >> 6;
        const float* w2p = w2 + (size_t)a * DD * HH + h;
        const float* yb  = c0 + b * DD;
        float ya = 0.f;
        #pragma unroll 8
        for (int d = q * 64; d < q * 64 + 64; d++) ya += yb[d] * w2p[(size_t)d * HH];
        red4[q][h] = ya;
    }

    float acc[4][8];
    #pragma unroll
    for (int i = 0; i < 4; i++)
        #pragma unroll
        for (int j = 0; j < 8; j++) acc[i][j] = 0.f;

    // Prefetch chunk 0 into registers
    float4 xv[2], wv;
    #pragma unroll
    for (int p = 0; p < 2; p++)
        xv[p] = *(const float4*)(xb + (size_t)(l4 + 64 * p) * DD + kk * 4);
    wv = *(const float4*)(wbase + (size_t)kwid * HH + hw * 4);

    __syncthreads();   // red4 ready
    {
        int h = tid & 63, q = tid >> 6;
        if (q == 0)
            ysv[h] = red4[0][h] + red4[1][h] + red4[2][h] + red4[3][h] + b2[a * HH + h];
    }

    // Stage chunk 0 into buffer 0
    #pragma unroll
    for (int p = 0; p < 2; p++) {
        int row = l4 + 64 * p;
        Xs[0][kk * 4 + 0][row] = xv[p].x;
        Xs[0][kk * 4 + 1][row] = xv[p].y;
        Xs[0][kk * 4 + 2][row] = xv[p].z;
        Xs[0][kk * 4 + 3][row] = xv[p].w;
    }
    *(float4*)&Wc[0][kwid][hw * 4] = wv;
    __syncthreads();

    for (int kc = 0; kc < 16; kc++) {
        const int buf = kc & 1;
        // Prefetch next chunk (latency overlaps the FFMA block below)
        if (kc < 15) {
            int koff = (kc + 1) * 16;
            #pragma unroll
            for (int p = 0; p < 2; p++)
                xv[p] = *(const float4*)(xb + (size_t)(l4 + 64 * p) * DD + koff + kk * 4);
            wv = *(const float4*)(wbase + (size_t)(koff + kwid) * HH + hw * 4);
        }

        #pragma unroll
        for (int k = 0; k < 16; k++) {
            float aa[4];
            #pragma unroll
            for (int i = 0; i < 4; i++) aa[i] = Xs[buf][k][rg + 32 * i];
            float4 w0 = *(const float4*)&Wc[buf][k][c8 * 8];
            float4 w1v = *(const float4*)&Wc[buf][k][c8 * 8 + 4];
            #pragma unroll
            for (int i = 0; i < 4; i++) {
                acc[i][0] += aa[i] * w0.x;  acc[i][1] += aa[i] * w0.y;
                acc[i][2] += aa[i] * w0.z;  acc[i][3] += aa[i] * w0.w;
                acc[i][4] += aa[i] * w1v.x; acc[i][5] += aa[i] * w1v.y;
                acc[i][6] += aa[i] * w1v.z; acc[i][7] += aa[i] * w1v.w;
            }
        }

        if (kc < 15) {
            const int nb = buf ^ 1;
            #pragma unroll
            for (int p = 0; p < 2; p++) {
                int row = l4 + 64 * p;
                Xs[nb][kk * 4 + 0][row] = xv[p].x;
                Xs[nb][kk * 4 + 1][row] = xv[p].y;
                Xs[nb][kk * 4 + 2][row] = xv[p].z;
                Xs[nb][kk * 4 + 3][row] = xv[p].w;
            }
            *(float4*)&Wc[nb][kwid][hw * 4] = wv;
            __syncthreads();
        }
    }

    // Epilogue: add b1, store z (STG.128), compute s-scores
    const int hb = c8 * 8;
    float4 bb0 = *(const float4*)(b1 + a * HH + hb);
    float4 bb1 = *(const float4*)(b1 + a * HH + hb + 4);
    float4 yt0 = *(const float4*)(&ysv[hb]);
    float4 yt1 = *(const float4*)(&ysv[hb + 4]);
    float4 vv0 = *(const float4*)(v + a * HH + hb);
    float4 vv1 = *(const float4*)(v + a * HH + hb + 4);

    float sp[4];
    #pragma unroll
    for (int i = 0; i < 4; i++) {
        int row = rg + 32 * i;
        float4 z0, z1;
        z0.x = acc[i][0] + bb0.x; z0.y = acc[i][1] + bb0.y;
        z0.z = acc[i][2] + bb0.z; z0.w = acc[i][3] + bb0.w;
        z1.x = acc[i][4] + bb1.x; z1.y = acc[i][5] + bb1.y;
        z1.z = acc[i][6] + bb1.z; z1.w = acc[i][7] + bb1.w;
        float* zr = g_z + ((size_t)b * LSEQ + l0 + row) * HH + hb;
        *(float4*)zr = z0;
        *(float4*)(zr + 4) = z1;
        float s;
        s  = vv0.x * fast_tanh(z0.x + yt0.x);
        s += vv0.y * fast_tanh(z0.y + yt0.y);
        s += vv0.z * fast_tanh(z0.z + yt0.z);
        s += vv0.w * fast_tanh(z0.w + yt0.w);
        s += vv1.x * fast_tanh(z1.x + yt1.x);
        s += vv1.y * fast_tanh(z1.y + yt1.y);
        s += vv1.z * fast_tanh(z1.z + yt1.z);
        s += vv1.w * fast_tanh(z1.w + yt1.w);
        sp[i] = s;
    }
    #pragma unroll
    for (int i = 0; i < 4; i++) {
        float s = sp[i];
        s += __shfl_xor_sync(0xffffffffu, s, 1);
        s += __shfl_xor_sync(0xffffffffu, s, 2);
        s += __shfl_xor_sync(0xffffffffu, s, 4);
        if (c8 == 0) {
            int l = l0 + rg + 32 * i;
            g_slog[b * LSEQ + l] = xmask[b * LSEQ + l] ? -1e30f : s;
        }
    }
}

// ---------------------------------------------------------------------------
// Row softmax over L=2048. which=0 -> g_slog, which=1 -> g_elog
// ---------------------------------------------------------------------------
__global__ __launch_bounds__(256) void k_softmax(int which, float* __restrict__ probs)
{
    __shared__ float red[256];
    int b = blockIdx.x, tid = threadIdx.x;
    const float* in = (which == 0 ? g_slog : g_elog) + b * LSEQ;
    float vals[8];
    float m = -INFINITY;
    #pragma unroll
    for (int i = 0; i < 8; i++) { vals[i] = in[tid + 256 * i]; m = fmaxf(m, vals[i]); }
    red[tid] = m; __syncthreads();
    for (int s = 128; s > 0; s >>= 1) { if (tid < s) red[tid] = fmaxf(red[tid], red[tid + s]); __syncthreads(); }
    m = red[0]; __syncthreads();
    float sum = 0.f;
    #pragma unroll
    for (int i = 0; i < 8; i++) { vals[i] = __expf(vals[i] - m); sum += vals[i]; }
    red[tid] = sum; __syncthreads();
    for (int s = 128; s > 0; s >>= 1) { if (tid < s) red[tid] += red[tid + s]; __syncthreads(); }
    float inv = 1.f / red[0];
    float* outp = probs + b * LSEQ;
    #pragma unroll
    for (int i = 0; i < 8; i++) outp[tid + 256 * i] = vals[i] * inv;
}

// ---------------------------------------------------------------------------
// attn_pool partials, four interleaved row-streams (16 LDG.128 in flight).
// grid (16, B), 256 threads: d4 = tid&63 owns a float4 of D; lg = tid>>6 owns
// 32 of the CTA's 128 l-rows (rows l, l+8, l+16, l+24 in parallel).
// ---------------------------------------------------------------------------
__global__ __launch_bounds__(256) void k_pool(const float* __restrict__ x,
                                              const float* __restrict__ probs)
{
    __shared__ float ps[128];
    int c = blockIdx.x, b = blockIdx.y, tid = threadIdx.x;
    int d4 = tid & 63, lg = tid >> 6;
    if (tid < 128) ps[tid] = probs[b * LSEQ + c * 128 + tid];
    __syncthreads();
    const float* xp = x + ((size_t)b * LSEQ + c * 128 + lg * 32) * DD + d4 * 4;
    const float* pp = ps + lg * 32;
    float4 aA = make_float4(0.f, 0.f, 0.f, 0.f);
    float4 aB = make_float4(0.f, 0.f, 0.f, 0.f);
    float4 aC = make_float4(0.f, 0.f, 0.f, 0.f);
    float4 aD = make_float4(0.f, 0.f, 0.f, 0.f);
    #pragma unroll
    for (int l = 0; l < 8; l += 2) {
        #pragma unroll
        for (int u = 0; u < 2; u++) {
            int li = l + u;
            float4 xa = *(const float4*)(xp + (size_t)li * DD);
            float4 xb2 = *(const float4*)(xp + (size_t)(li + 8) * DD);
            float4 xc = *(const float4*)(xp + (size_t)(li + 16) * DD);
            float4 xd = *(const float4*)(xp + (size_t)(li + 24) * DD);
            float pa = pp[li], pb = pp[li + 8], pc = pp[li + 16], pd = pp[li + 24];
            aA.x += xa.x * pa; aA.y += xa.y * pa; aA.z += xa.z * pa; aA.w += xa.w * pa;
            aB.x += xb2.x * pb; aB.y += xb2.y * pb; aB.z += xb2.z * pb; aB.w += xb2.w * pb;
            aC.x += xc.x * pc; aC.y += xc.y * pc; aC.z += xc.z * pc; aC.w += xc.w * pc;
            aD.x += xd.x * pd; aD.y += xd.y * pd; aD.z += xd.z * pd; aD.w += xd.w * pd;
        }
    }
    aA.x = (aA.x + aB.x) + (aC.x + aD.x);
    aA.y = (aA.y + aB.y) + (aC.y + aD.y);
    aA.z = (aA.z + aB.z) + (aC.z + aD.z);
    aA.w = (aA.w + aB.w) + (aC.w + aD.w);
    *(float4*)(&g_pool_part[((size_t)(b * 16 + c) * 4 + lg) * DD + d4 * 4]) = aA;
}

// ---------------------------------------------------------------------------
// SRU cell + y_te, latency-optimized. 1024 threads, one CTA per batch
// (64-reg budget so ptxas can keep many loads in flight).
// Phase A: 4-way partial split, 16 independent loads/thread.
// Phase B: u[col] with 2-way d-split x 4 accumulators, fully unrolled.
// Phase C: y_te with 16-way d-split + smem tree.
// ---------------------------------------------------------------------------
__global__ __launch_bounds__(1024, 1) void k_sru(const float* __restrict__ c0,
    const float* __restrict__ w_sru, const float* __restrict__ b_sru,
    const int* __restrict__ actions,
    const float* __restrict__ w2, const float* __restrict__ b2)
{
    __shared__ float pool[DD];
    __shared__ float scratch[1024];
    __shared__ float uu[2 * YY];
    __shared__ float state[YY];
    __shared__ float red16[16][HH];
    const int b = blockIdx.x, tid = threadIdx.x;

    // ---- Phase A: pool[d] = sum_{p<64} pool_part[b][p][d]; 4-way p-split.
    {
        int d = tid & 255, s = tid >> 8;   // s in 0..3 -> partials [16s, 16s+16)
        const float* pp = g_pool_part + (size_t)b * NP * DD + (size_t)s * 16 * DD + d;
        float a0 = 0.f, a1 = 0.f, a2 = 0.f, a3 = 0.f;
        #pragma unroll
        for (int c = 0; c < 16; c += 4) {
            a0 += pp[(size_t)c * DD];
            a1 += pp[(size_t)(c + 1) * DD];
            a2 += pp[(size_t)(c + 2) * DD];
            a3 += pp[(size_t)(c + 3) * DD];
        }
        scratch[tid] = (a0 + a1) + (a2 + a3);
    }
    __syncthreads();
    if (tid < DD)
        pool[tid] = (scratch[tid] + scratch[tid + 256])
                  + (scratch[tid + 512] + scratch[tid + 768]);
    __syncthreads();

    // ---- Phase B: u[col] = sum_d pool[d] * w_sru[d][col], col < 512.
    // 2-way d-split (q = tid>>9), 4 accumulators, fully unrolled.
    {
        int col = tid & 511, q = tid >> 9;
        const float* wp = w_sru + (size_t)(q * 128) * 768 + col;
        const float* pq = pool + q * 128;
        float a0 = 0.f, a1 = 0.f, a2 = 0.f, a3 = 0.f;
        #pragma unroll
        for (int d = 0; d < 128; d += 4) {
            a0 += pq[d]     * wp[(size_t)d * 768];
            a1 += pq[d + 1] * wp[(size_t)(d + 1) * 768];
            a2 += pq[d + 2] * wp[(size_t)(d + 2) * 768];
            a3 += pq[d + 3] * wp[(size_t)(d + 3) * 768];
        }
        scratch[tid] = (a0 + a1) + (a2 + a3);
    }
    __syncthreads();
    if (tid < 512) uu[tid] = scratch[tid] + scratch[tid + 512];
    __syncthreads();
    if (tid < YY) {
        float f = 1.f / (1.f + __expf(-(uu[YY + tid] + b_sru[tid])));
        state[tid] = f * c0[b * DD + tid] + (1.f - f) * uu[tid];
    }
    __syncthreads();

    // ---- Phase C: y_te[h] = sum_d state[d] * w2[a][d][h], 16-way d-split.
    const int a = actions[b];
    {
        int h = tid & 63, q = tid >> 6;   // q in 0..15
        const float* w = w2 + (size_t)a * DD * HH + (size_t)(q * 16) * HH + h;
        const float* sq = state + q * 16;
        float yt = 0.f;
        #pragma unroll
        for (int d = 0; d < 16; d++) yt += sq[d] * w[(size_t)d * HH];
        red16[q][h] = yt;
    }
    __syncthreads();
    if (tid < HH) {
        float s = 0.f;
        #pragma unroll
        for (int q2 = 0; q2 < 16; q2++) s += red16[q2][tid];
        g_yte[b * HH + tid] = s + b2[a * HH + tid];
    }
}

// ---------------------------------------------------------------------------
// e-scores from cached z. float2 per lane, 4 rows per warp (32 rows per CTA).
// ---------------------------------------------------------------------------
__global__ __launch_bounds__(256) void k_escore(const unsigned char* __restrict__ xmask,
    const int* __restrict__ actions, const float* __restrict__ v)
{
    int b = blockIdx.y;
    int wid = threadIdx.x >> 5, lane = threadIdx.x & 31;
    int a = actions[b];
    float2 yv = *(const float2*)(&g_yte[b * HH + 2 * lane]);
    float2 vv = *(const float2*)(v + a * HH + 2 * lane);
    #pragma unroll
    for (int r = 0; r < 4; r++) {
        int l = blockIdx.x * 32 + wid * 4 + r;
        float2 z2 = *(const float2*)(&g_z[((size_t)b * LSEQ + l) * HH + 2 * lane]);
        float s = vv.x * fast_tanh(z2.x + yv.x) + vv.y * fast_tanh(z2.y + yv.y);
        #pragma unroll
        for (int o = 16; o > 0; o >>= 1) s += __shfl_xor_sync(0xffffffffu, s, o);
        if (lane == 0) g_elog[b * LSEQ + l] = xmask[b * LSEQ + l] ? -1e30f : s;
    }
}

// ---------------------------------------------------------------------------
extern "C" void kernel_launch(void* const* d_in, const int* in_sizes, int n_in,
                              void* d_out, int out_size)
{
    const float*         x      = (const float*)d_in[0];
    const unsigned char* xmask  = (const unsigned char*)d_in[1];
    const float*         c0     = (const float*)d_in[2];
    const int*           actions= (const int*)d_in[3];
    const float*         w1     = (const float*)d_in[4];
    const float*         b1     = (const float*)d_in[5];
    const float*         w2     = (const float*)d_in[6];
    const float*         b2     = (const float*)d_in[7];
    const float*         v      = (const float*)d_in[8];
    const float*         w_sru  = (const float*)d_in[9];
    const float*         b_sru  = (const float*)d_in[10];
    float* out = (float*)d_out;   // [0:65536) = s_probs, [65536:131072) = e_probs

    k_gemm_score<<<dim3(LSEQ / 128, BB), 256>>>(x, xmask, actions, w1, b1, v, c0, w2, b2);
    k_softmax<<<BB, 256>>>(0, out);                        // s_probs
    k_pool<<<dim3(16, BB), 256>>>(x, out);
    k_sru<<<BB, 1024>>>(c0, w_sru, b_sru, actions, w2, b2);
    k_escore<<<dim3(LSEQ / 32, BB), 256>>>(xmask, actions, v);
    k_softmax<<<BB, 256>>>(1, out + BB * LSEQ);            // e_probs
}